// round 15
// baseline (speedup 1.0000x reference)
#include <cuda_runtime.h>
#include <cuda_bf16.h>
#include <cstdint>

#define B_ 16
#define C_ 512
#define N_ 2048
#define D_ 64

// ---------------- scratch (device globals; allocation-free) ----------------
__device__ __nv_bfloat16 g_xT  [(size_t)B_ * N_ * C_];
__device__ __nv_bfloat16 g_Wqk [128 * C_];               // rows 0-63 Wq, 64-127 Wk
__device__ __nv_bfloat16 g_Wv  [C_ * C_];
__device__ __nv_bfloat16 g_q   [(size_t)B_ * N_ * D_];
__device__ __nv_bfloat16 g_k   [(size_t)B_ * N_ * D_];
__device__ uint8_t       g_v   [(size_t)B_ * C_ * N_];   // e4m3      16 MB
__device__ uint8_t       g_attn[(size_t)B_ * N_ * N_];   // e5m2 exp  64 MB
__device__ float         g_rowsum[(size_t)B_ * N_];

// ============================================================================
// GEMM engine (R12): CTA tile 128x128, 128 threads = 4 warps (2M x 2N),
// warp tile 64x64, fp32 accumulate, ldmatrix.x4, 4-stage cp.async, 80B rows.
// bf16 path: m16n8k16, BK=32 (64B chunk rows).
// fp8 path (out GEMM): m16n8k32 e4m3 x e5m2, BK=64 — byte-identical chunks,
// half the chunks and 2x FLOP per MMA.
// ============================================================================
#define ROWB 80
#define STAGE_BYTES (128 * ROWB)             // 10240
#define NSTAGE 4
#define SUMS_BYTE_OFF (2 * NSTAGE * STAGE_BYTES)   // 81920
#define SMEM_BYTES (SUMS_BYTE_OFF + 512)           // 82432 -> 2 CTAs/SM

__device__ __forceinline__ uint32_t smem_u32(const void* p) {
    uint32_t a;
    asm("{ .reg .u64 t; cvta.to.shared.u64 t, %1; cvt.u32.u64 %0, t; }"
        : "=r"(a) : "l"(p));
    return a;
}
__device__ __forceinline__ void cp16(uint32_t s, const void* g) {
    asm volatile("cp.async.cg.shared.global [%0], [%1], 16;"
                 :: "r"(s), "l"(g) : "memory");
}
#define CP_COMMIT() asm volatile("cp.async.commit_group;" ::: "memory")
#define CP_WAIT0()  asm volatile("cp.async.wait_group 0;" ::: "memory")
#define CP_WAIT1()  asm volatile("cp.async.wait_group 1;" ::: "memory")
#define CP_WAIT2()  asm volatile("cp.async.wait_group 2;" ::: "memory")

__device__ __forceinline__ void mma_bf16(float* c, const uint32_t* a, const uint32_t* b) {
    asm volatile(
        "mma.sync.aligned.m16n8k16.row.col.f32.bf16.bf16.f32 "
        "{%0,%1,%2,%3}, {%4,%5,%6,%7}, {%8,%9}, {%0,%1,%2,%3};"
        : "+f"(c[0]), "+f"(c[1]), "+f"(c[2]), "+f"(c[3])
        : "r"(a[0]), "r"(a[1]), "r"(a[2]), "r"(a[3]), "r"(b[0]), "r"(b[1]));
}
__device__ __forceinline__ void mma_fp8(float* c, const uint32_t* a, const uint32_t* b) {
    asm volatile(
        "mma.sync.aligned.m16n8k32.row.col.f32.e4m3.e5m2.f32 "
        "{%0,%1,%2,%3}, {%4,%5,%6,%7}, {%8,%9}, {%0,%1,%2,%3};"
        : "+f"(c[0]), "+f"(c[1]), "+f"(c[2]), "+f"(c[3])
        : "r"(a[0]), "r"(a[1]), "r"(a[2]), "r"(a[3]), "r"(b[0]), "r"(b[1]));
}
__device__ __forceinline__ void ldsm_x4(uint32_t* r, uint32_t addr) {
    asm volatile("ldmatrix.sync.aligned.m8n8.x4.shared.b16 {%0,%1,%2,%3}, [%4];"
        : "=r"(r[0]), "=r"(r[1]), "=r"(r[2]), "=r"(r[3]) : "r"(addr));
}
__device__ __forceinline__ uint32_t packbf(float lo, float hi) {
    uint32_t r;
    asm("cvt.rn.bf16x2.f32 %0, %1, %2;" : "=r"(r) : "f"(hi), "f"(lo));
    return r;
}
__device__ __forceinline__ uint16_t packe4(float lo, float hi) {
    uint16_t r;
    asm("cvt.rn.satfinite.e4m3x2.f32 %0, %1, %2;" : "=h"(r) : "f"(hi), "f"(lo));
    return r;
}
__device__ __forceinline__ uint16_t packe5(float lo, float hi) {
    uint16_t r;
    asm("cvt.rn.satfinite.e5m2x2.f32 %0, %1, %2;" : "=h"(r) : "f"(hi), "f"(lo));
    return r;
}

// ---- bf16 load: one 128x32(bf16) A chunk and B chunk into stage st ----
__device__ __forceinline__ void load_stage(
    uint32_t smu, int st,
    const __nv_bfloat16* __restrict__ A, int lda,
    const __nv_bfloat16* __restrict__ B, int ldb, int kc)
{
    const int tid = threadIdx.x;
    const uint32_t a_base = smu + (uint32_t)(st * STAGE_BYTES);
    const uint32_t b_base = smu + (uint32_t)((NSTAGE + st) * STAGE_BYTES);
    const __nv_bfloat16* Ak = A + kc * 32;
    const __nv_bfloat16* Bk = B + kc * 32;
    #pragma unroll
    for (int t = 0; t < 4; t++) {
        int idx = tid + t * 128;
        int r = idx >> 2, c = idx & 3;
        cp16(a_base + (uint32_t)(r * ROWB + c * 16), Ak + (size_t)r * lda + c * 8);
    }
    #pragma unroll
    for (int t = 0; t < 4; t++) {
        int idx = tid + t * 128;
        int r = idx >> 2, c = idx & 3;
        cp16(b_base + (uint32_t)(r * ROWB + c * 16), Bk + (size_t)r * ldb + c * 8);
    }
}

// ---- fp8 load: one 128x64(fp8) A chunk and B chunk (byte addressing) ----
__device__ __forceinline__ void load_stage_f8(
    uint32_t smu, int st,
    const uint8_t* __restrict__ A, int lda,
    const uint8_t* __restrict__ B, int ldb, int kc)
{
    const int tid = threadIdx.x;
    const uint32_t a_base = smu + (uint32_t)(st * STAGE_BYTES);
    const uint32_t b_base = smu + (uint32_t)((NSTAGE + st) * STAGE_BYTES);
    const uint8_t* Ak = A + kc * 64;
    const uint8_t* Bk = B + kc * 64;
    #pragma unroll
    for (int t = 0; t < 4; t++) {
        int idx = tid + t * 128;
        int r = idx >> 2, c = idx & 3;
        cp16(a_base + (uint32_t)(r * ROWB + c * 16), Ak + (size_t)r * lda + c * 16);
    }
    #pragma unroll
    for (int t = 0; t < 4; t++) {
        int idx = tid + t * 128;
        int r = idx >> 2, c = idx & 3;
        cp16(b_base + (uint32_t)(r * ROWB + c * 16), Bk + (size_t)r * ldb + c * 16);
    }
}

// ---- compute: byte-identical addressing for bf16(k16) and fp8(k32) ----
template <bool FP8>
__device__ __forceinline__ void compute_stage(
    uint32_t smu, int st, int wm, int wn, int lane, float acc[4][8][4])
{
    const uint32_t As = smu + (uint32_t)(st * STAGE_BYTES);
    const uint32_t Bs = smu + (uint32_t)((NSTAGE + st) * STAGE_BYTES);
    const uint32_t aoff = As + (uint32_t)((wm * 64 + (lane & 15)) * ROWB + (lane >> 4) * 16);
    const int s = lane >> 3;
    const uint32_t boff = Bs + (uint32_t)((wn * 64 + (s >> 1) * 8 + (lane & 7)) * ROWB + (s & 1) * 16);
    #pragma unroll
    for (int ks = 0; ks < 2; ks++) {       // 2 x 32B halves of the 64B row
        uint32_t a[4][4], b[4][4];
        #pragma unroll
        for (int mt = 0; mt < 4; mt++)
            ldsm_x4(a[mt], aoff + (uint32_t)(mt * 16 * ROWB + ks * 32));
        #pragma unroll
        for (int np = 0; np < 4; np++)
            ldsm_x4(b[np], boff + (uint32_t)(np * 16 * ROWB + ks * 32));
        #pragma unroll
        for (int mt = 0; mt < 4; mt++) {
            #pragma unroll
            for (int np = 0; np < 4; np++) {
                if (FP8) {
                    mma_fp8(acc[mt][np * 2],     a[mt], &b[np][0]);
                    mma_fp8(acc[mt][np * 2 + 1], a[mt], &b[np][2]);
                } else {
                    mma_bf16(acc[mt][np * 2],     a[mt], &b[np][0]);
                    mma_bf16(acc[mt][np * 2 + 1], a[mt], &b[np][2]);
                }
            }
        }
    }
}

// ---- bf16 4-stage mainloop (prefetch 3) ----
__device__ __forceinline__ void run_gemm(
    const __nv_bfloat16* __restrict__ A, int lda,
    const __nv_bfloat16* __restrict__ B, int ldb, int nk,
    uint32_t smu, int wm, int wn, int lane, float acc[4][8][4])
{
    const int pf = (nk < 3) ? nk : 3;
    for (int st = 0; st < pf; st++) {
        load_stage(smu, st, A, lda, B, ldb, st);
        CP_COMMIT();
    }
    for (int kc = 0; kc < nk; kc++) {
        const int rem = nk - 1 - kc;
        if (rem >= 2) CP_WAIT2();
        else if (rem == 1) CP_WAIT1();
        else CP_WAIT0();
        __syncthreads();
        compute_stage<false>(smu, kc & 3, wm, wn, lane, acc);
        const int nxt = kc + 3;
        if (nxt < nk) {
            load_stage(smu, nxt & 3, A, lda, B, ldb, nxt);
            CP_COMMIT();
        }
    }
}

// ---- fp8 4-stage mainloop (prefetch 3) ----
__device__ __forceinline__ void run_gemm_f8(
    const uint8_t* __restrict__ A, int lda,
    const uint8_t* __restrict__ B, int ldb, int nk,
    uint32_t smu, int wm, int wn, int lane, float acc[4][8][4])
{
    const int pf = (nk < 3) ? nk : 3;
    for (int st = 0; st < pf; st++) {
        load_stage_f8(smu, st, A, lda, B, ldb, st);
        CP_COMMIT();
    }
    for (int kc = 0; kc < nk; kc++) {
        const int rem = nk - 1 - kc;
        if (rem >= 2) CP_WAIT2();
        else if (rem == 1) CP_WAIT1();
        else CP_WAIT0();
        __syncthreads();
        compute_stage<true>(smu, kc & 3, wm, wn, lane, acc);
        const int nxt = kc + 3;
        if (nxt < nk) {
            load_stage_f8(smu, nxt & 3, A, lda, B, ldb, nxt);
            CP_COMMIT();
        }
    }
}

#define GEMM_PREAMBLE() \
    extern __shared__ __align__(16) float sm[]; \
    const uint32_t smu = smem_u32(sm); \
    const int tid = threadIdx.x; \
    const int wid = tid >> 5, lane = tid & 31; \
    const int wm = wid & 1, wn = wid >> 1; \
    const int g = lane >> 2, q4 = lane & 3; \
    float acc[4][8][4]; \
    _Pragma("unroll") for (int i = 0; i < 4; i++) \
    _Pragma("unroll") for (int j = 0; j < 8; j++) \
    _Pragma("unroll") for (int l = 0; l < 4; l++) acc[i][j][l] = 0.f;

#define NT_COL(nt) (wn * 64 + ((nt) >> 1) * 16 + ((nt) & 1) * 8 + q4 * 2)

// ============================================================================
// Kernel 0a: zero g_rowsum
// ============================================================================
__global__ void zero_rowsum_kernel() {
    g_rowsum[blockIdx.x * 1024 + threadIdx.x] = 0.f;
}

// ============================================================================
// Kernel 0b: convert weights fp32 -> bf16 ([Wq;Wk] stacked, Wv)
// ============================================================================
__global__ void convert_w_kernel(const float* __restrict__ Wq,
                                 const float* __restrict__ Wk,
                                 const float* __restrict__ Wv) {
    const int t = blockIdx.x * 256 + threadIdx.x;   // 81920 float4 items
    const float* src;
    __nv_bfloat16* dst;
    int off;
    if (t < 8192)       { src = Wq; dst = g_Wqk;            off = t; }
    else if (t < 16384) { src = Wk; dst = g_Wqk + 64 * C_;  off = t - 8192; }
    else                { src = Wv; dst = g_Wv;             off = t - 16384; }
    float4 v = ((const float4*)src)[off];
    uint32_t* d = (uint32_t*)dst + off * 2;
    d[0] = packbf(v.x, v.y);
    d[1] = packbf(v.z, v.w);
}

// ============================================================================
// Kernel 1: x transpose  x[b][c][n] fp32 -> xT[b][n][c] bf16
// ============================================================================
__global__ void transpose_kernel(const float* __restrict__ x) {
    __shared__ float t[32][33];
    const int b = blockIdx.z;
    const int n0 = blockIdx.x * 32, c0 = blockIdx.y * 32;
    const float* xb = x + (size_t)b * C_ * N_;
    __nv_bfloat16* xtb = g_xT + (size_t)b * N_ * C_;
    const int tx = threadIdx.x, ty = threadIdx.y;   // 32 x 8
    #pragma unroll
    for (int i = 0; i < 32; i += 8)
        t[ty + i][tx] = xb[(size_t)(c0 + ty + i) * N_ + n0 + tx];
    __syncthreads();
    #pragma unroll
    for (int i = 0; i < 32; i += 8)
        xtb[(size_t)(n0 + ty + i) * C_ + c0 + tx] = __float2bfloat16(t[tx][ty + i]);
}

// ============================================================================
// Kernel 2: fused q+k projection.  M=n(128), N=128([Wq;Wk]), K=512.  (bf16)
// ============================================================================
__global__ void __launch_bounds__(128, 2)
qk_proj_kernel(const float* __restrict__ bq, const float* __restrict__ bk) {
    GEMM_PREAMBLE();
    const int b = blockIdx.z;
    const int n0 = blockIdx.x * 128;

    const __nv_bfloat16* A = g_xT + ((size_t)b * N_ + n0) * C_;
    run_gemm(A, C_, g_Wqk, C_, C_ / 32, smu, wm, wn, lane, acc);

    const size_t qkbase = (size_t)b * N_ + n0;
    #pragma unroll
    for (int mt = 0; mt < 4; mt++) {
        const int r0 = wm * 64 + mt * 16 + g;
        #pragma unroll
        for (int nt = 0; nt < 8; nt++) {
            const int col = NT_COL(nt);
            const bool isq = (col < 64);
            const int d = isq ? col : col - 64;
            const float bv0 = isq ? __ldg(bq + d)     : __ldg(bk + d);
            const float bv1 = isq ? __ldg(bq + d + 1) : __ldg(bk + d + 1);
            __nv_bfloat16* dst = isq ? g_q : g_k;
            *(uint32_t*)&dst[(qkbase + r0) * D_ + d] =
                packbf(acc[mt][nt][0] + bv0, acc[mt][nt][1] + bv1);
            *(uint32_t*)&dst[(qkbase + r0 + 8) * D_ + d] =
                packbf(acc[mt][nt][2] + bv0, acc[mt][nt][3] + bv1);
        }
    }
}

// ============================================================================
// Kernel 3: v projection (bf16 mainloop, e4m3 output).  M=c(128), N=n(128).
// ============================================================================
__global__ void __launch_bounds__(128, 2)
v_proj_kernel(const float* __restrict__ bv) {
    GEMM_PREAMBLE();
    const int b = blockIdx.z;
    const int n0 = blockIdx.x * 128;
    const int c0 = blockIdx.y * 128;

    const __nv_bfloat16* A = g_Wv + (size_t)c0 * C_;
    const __nv_bfloat16* Bm = g_xT + ((size_t)b * N_ + n0) * C_;
    run_gemm(A, C_, Bm, C_, C_ / 32, smu, wm, wn, lane, acc);

    #pragma unroll
    for (int mt = 0; mt < 4; mt++) {
        const int r0 = wm * 64 + mt * 16 + g;
        const float bia0 = __ldg(bv + c0 + r0);
        const float bia8 = __ldg(bv + c0 + r0 + 8);
        uint8_t* row0 = g_v + ((size_t)b * C_ + c0 + r0) * N_ + n0;
        uint8_t* row8 = row0 + (size_t)8 * N_;
        #pragma unroll
        for (int nt = 0; nt < 8; nt++) {
            const int col = NT_COL(nt);
            *(uint16_t*)&row0[col] = packe4(acc[mt][nt][0] + bia0, acc[mt][nt][1] + bia0);
            *(uint16_t*)&row8[col] = packe4(acc[mt][nt][2] + bia8, acc[mt][nt][3] + bia8);
        }
    }
}

// ============================================================================
// Kernel 4: energy + exp + row-sum (bf16 mainloop, e5m2 output).
// P = exp(e) in [~6e-6, ~2e4] fits e5m2 range without scaling.
// rowsum accumulated in exact fp32.
// ============================================================================
__global__ void __launch_bounds__(128, 2)
energy_kernel() {
    GEMM_PREAMBLE();
    const int b = blockIdx.z;
    const int j0 = blockIdx.x * 128;
    const int i0 = blockIdx.y * 128;

    float* sums = (float*)((char*)sm + SUMS_BYTE_OFF);
    if (tid < 128) sums[tid] = 0.f;

    const __nv_bfloat16* A = g_q + ((size_t)b * N_ + i0) * D_;
    const __nv_bfloat16* Bm = g_k + ((size_t)b * N_ + j0) * D_;
    run_gemm(A, D_, Bm, D_, D_ / 32, smu, wm, wn, lane, acc);
    __syncthreads();

    #pragma unroll
    for (int mt = 0; mt < 4; mt++) {
        const int r0 = wm * 64 + mt * 16 + g;
        uint8_t* row0 = g_attn + ((size_t)b * N_ + i0 + r0) * N_ + j0;
        uint8_t* row8 = row0 + (size_t)8 * N_;
        float p0 = 0.f, p1 = 0.f;
        #pragma unroll
        for (int nt = 0; nt < 8; nt++) {
            const int col = NT_COL(nt);
            float e0 = __expf(acc[mt][nt][0]);
            float e1 = __expf(acc[mt][nt][1]);
            float e2 = __expf(acc[mt][nt][2]);
            float e3 = __expf(acc[mt][nt][3]);
            *(uint16_t*)&row0[col] = packe5(e0, e1);
            *(uint16_t*)&row8[col] = packe5(e2, e3);
            p0 += e0 + e1;
            p1 += e2 + e3;
        }
        p0 += __shfl_xor_sync(0xffffffffu, p0, 1);
        p0 += __shfl_xor_sync(0xffffffffu, p0, 2);
        p1 += __shfl_xor_sync(0xffffffffu, p1, 1);
        p1 += __shfl_xor_sync(0xffffffffu, p1, 2);
        if (q4 == 0) {
            atomicAdd(&sums[r0], p0);
            atomicAdd(&sums[r0 + 8], p1);
        }
    }
    __syncthreads();
    if (tid < 128)
        atomicAdd(&g_rowsum[(size_t)b * N_ + i0 + tid], sums[tid]);
}

// ============================================================================
// Kernel 5: out GEMM (FP8: A = v e4m3, B = P e5m2, m16n8k32).
// out[c][i] = gamma/rowsum[i] * sum_j v[c][j] P[i][j] + x[c][i].
// M=c(128), N=i(128), K=2048 in 32 chunks of 64.
// ============================================================================
__global__ void __launch_bounds__(128, 2)
out_kernel(const float* __restrict__ x, const float* __restrict__ gamma,
           float* __restrict__ out) {
    GEMM_PREAMBLE();
    const int b = blockIdx.z;
    const int i0 = blockIdx.x * 128;
    const int c0 = blockIdx.y * 128;

    const uint8_t* A = g_v + ((size_t)b * C_ + c0) * N_;
    const uint8_t* Bm = g_attn + ((size_t)b * N_ + i0) * N_;
    run_gemm_f8(A, N_, Bm, N_, N_ / 64, smu, wm, wn, lane, acc);

    const float gm = __ldg(gamma);
    float sc[8][2];
    #pragma unroll
    for (int nt = 0; nt < 8; nt++) {
        const int col = i0 + NT_COL(nt);
        sc[nt][0] = gm / __ldg(&g_rowsum[(size_t)b * N_ + col]);
        sc[nt][1] = gm / __ldg(&g_rowsum[(size_t)b * N_ + col + 1]);
    }

    #pragma unroll
    for (int mt = 0; mt < 4; mt++) {
        const int r0 = wm * 64 + mt * 16 + g;
        const size_t base0 = ((size_t)b * C_ + c0 + r0) * N_ + i0;
        const size_t base8 = base0 + (size_t)8 * N_;
        #pragma unroll
        for (int nt = 0; nt < 8; nt++) {
            const int col = NT_COL(nt);
            float2 x0 = *(const float2*)&x[base0 + col];
            float2 x8 = *(const float2*)&x[base8 + col];
            *(float2*)&out[base0 + col] =
                make_float2(sc[nt][0] * acc[mt][nt][0] + x0.x,
                            sc[nt][1] * acc[mt][nt][1] + x0.y);
            *(float2*)&out[base8 + col] =
                make_float2(sc[nt][0] * acc[mt][nt][2] + x8.x,
                            sc[nt][1] * acc[mt][nt][3] + x8.y);
        }
    }
}

// ============================================================================
// Launch — R12 topology (serial prologue; v_proj overlaps qk_proj -> energy).
// ============================================================================
extern "C" void kernel_launch(void* const* d_in, const int* in_sizes, int n_in,
                              void* d_out, int out_size) {
    (void)in_sizes; (void)n_in; (void)out_size;
    const float* x     = (const float*)d_in[0];
    const float* Wq    = (const float*)d_in[1];
    const float* bq    = (const float*)d_in[2];
    const float* Wk    = (const float*)d_in[3];
    const float* bk    = (const float*)d_in[4];
    const float* Wv    = (const float*)d_in[5];
    const float* bv    = (const float*)d_in[6];
    const float* gamma = (const float*)d_in[7];
    float* out = (float*)d_out;

    static cudaStream_t s1 = nullptr;
    static cudaEvent_t ev_fork = nullptr, ev_join = nullptr;
    static bool init_done = false;
    if (!init_done) {
        cudaFuncSetAttribute(qk_proj_kernel, cudaFuncAttributeMaxDynamicSharedMemorySize, SMEM_BYTES);
        cudaFuncSetAttribute(v_proj_kernel,  cudaFuncAttributeMaxDynamicSharedMemorySize, SMEM_BYTES);
        cudaFuncSetAttribute(energy_kernel,  cudaFuncAttributeMaxDynamicSharedMemorySize, SMEM_BYTES);
        cudaFuncSetAttribute(out_kernel,     cudaFuncAttributeMaxDynamicSharedMemorySize, SMEM_BYTES);
        cudaStreamCreateWithFlags(&s1, cudaStreamNonBlocking);
        cudaEventCreateWithFlags(&ev_fork, cudaEventDisableTiming);
        cudaEventCreateWithFlags(&ev_join, cudaEventDisableTiming);
        init_done = true;
    }

    // prologue (stream 0)
    zero_rowsum_kernel<<<B_ * N_ / 1024, 1024>>>();
    convert_w_kernel<<<320, 256>>>(Wq, Wk, Wv);
    transpose_kernel<<<dim3(N_ / 32, C_ / 32, B_), dim3(32, 8)>>>(x);

    // fork: qk_proj -> energy on s1, v_proj on stream 0
    cudaEventRecord(ev_fork, 0);
    cudaStreamWaitEvent(s1, ev_fork, 0);
    qk_proj_kernel<<<dim3(N_ / 128, 1, B_), 128, SMEM_BYTES, s1>>>(bq, bk);
    energy_kernel<<<dim3(N_ / 128, N_ / 128, B_), 128, SMEM_BYTES, s1>>>();
    v_proj_kernel<<<dim3(N_ / 128, C_ / 128, B_), 128, SMEM_BYTES>>>(bv);

    // join: out waits on both branches
    cudaEventRecord(ev_join, s1);
    cudaStreamWaitEvent(0, ev_join, 0);
    out_kernel<<<dim3(N_ / 128, N_ / 128 / 4, B_), 128, SMEM_BYTES>>>(x, gamma, out);
}

// round 16
// speedup vs baseline: 1.1479x; 1.1479x over previous
#include <cuda_runtime.h>
#include <cuda_bf16.h>
#include <cstdint>

#define B_ 16
#define C_ 512
#define N_ 2048
#define D_ 64

// ---------------- scratch (device globals; allocation-free) ----------------
__device__ __nv_bfloat16 g_xT  [(size_t)B_ * N_ * C_];
__device__ __nv_bfloat16 g_Wqk [128 * C_];               // rows 0-63 Wq, 64-127 Wk
__device__ __nv_bfloat16 g_Wv  [C_ * C_];
__device__ __nv_bfloat16 g_q   [(size_t)B_ * N_ * D_];
__device__ __nv_bfloat16 g_k   [(size_t)B_ * N_ * D_];
__device__ __nv_bfloat16 g_v   [(size_t)B_ * C_ * N_];
__device__ __nv_bfloat16 g_attn[(size_t)B_ * N_ * N_];
__device__ float         g_rowsum[(size_t)B_ * N_];

// ============================================================================
// bf16 mma.sync GEMM engine v2 (R12 == measured best, 363.2us):
// CTA tile 128x128, BK=32, 128 threads = 4 warps (2M x 2N), warp tile 64x64,
// m16n8k16, fp32 accumulate. Fragment duplication A x2 + B x2.
// ldmatrix.x4 loads, 4-stage cp.async (.cg) pipeline, 80B-padded rows.
// 82KB smem/CTA -> 2 CTAs/SM with 64KB L1 retained.
// ============================================================================
#define ROWB 80
#define STAGE_BYTES (128 * ROWB)             // 10240
#define NSTAGE 4
#define SUMS_BYTE_OFF (2 * NSTAGE * STAGE_BYTES)   // 81920
#define SMEM_BYTES (SUMS_BYTE_OFF + 512)           // 82432 -> 2 CTAs/SM

__device__ __forceinline__ uint32_t smem_u32(const void* p) {
    uint32_t a;
    asm("{ .reg .u64 t; cvta.to.shared.u64 t, %1; cvt.u32.u64 %0, t; }"
        : "=r"(a) : "l"(p));
    return a;
}
__device__ __forceinline__ void cp16(uint32_t s, const void* g) {
    asm volatile("cp.async.cg.shared.global [%0], [%1], 16;"
                 :: "r"(s), "l"(g) : "memory");
}
#define CP_COMMIT() asm volatile("cp.async.commit_group;" ::: "memory")
#define CP_WAIT0()  asm volatile("cp.async.wait_group 0;" ::: "memory")
#define CP_WAIT1()  asm volatile("cp.async.wait_group 1;" ::: "memory")
#define CP_WAIT2()  asm volatile("cp.async.wait_group 2;" ::: "memory")

__device__ __forceinline__ void mma_bf16(float* c, const uint32_t* a, const uint32_t* b) {
    asm volatile(
        "mma.sync.aligned.m16n8k16.row.col.f32.bf16.bf16.f32 "
        "{%0,%1,%2,%3}, {%4,%5,%6,%7}, {%8,%9}, {%0,%1,%2,%3};"
        : "+f"(c[0]), "+f"(c[1]), "+f"(c[2]), "+f"(c[3])
        : "r"(a[0]), "r"(a[1]), "r"(a[2]), "r"(a[3]), "r"(b[0]), "r"(b[1]));
}
__device__ __forceinline__ void ldsm_x4(uint32_t* r, uint32_t addr) {
    asm volatile("ldmatrix.sync.aligned.m8n8.x4.shared.b16 {%0,%1,%2,%3}, [%4];"
        : "=r"(r[0]), "=r"(r[1]), "=r"(r[2]), "=r"(r[3]) : "r"(addr));
}
__device__ __forceinline__ uint32_t packbf(float lo, float hi) {
    uint32_t r;
    asm("cvt.rn.bf16x2.f32 %0, %1, %2;" : "=r"(r) : "f"(hi), "f"(lo));
    return r;
}

// Load one 128x32(bf16) A chunk and B chunk into stage `st` (128 threads).
__device__ __forceinline__ void load_stage(
    uint32_t smu, int st,
    const __nv_bfloat16* __restrict__ A, int lda,
    const __nv_bfloat16* __restrict__ B, int ldb, int kc)
{
    const int tid = threadIdx.x;
    const uint32_t a_base = smu + (uint32_t)(st * STAGE_BYTES);
    const uint32_t b_base = smu + (uint32_t)((NSTAGE + st) * STAGE_BYTES);
    const __nv_bfloat16* Ak = A + kc * 32;
    const __nv_bfloat16* Bk = B + kc * 32;
    #pragma unroll
    for (int t = 0; t < 4; t++) {
        int idx = tid + t * 128;           // 0..511
        int r = idx >> 2, c = idx & 3;     // row, 16B chunk
        cp16(a_base + (uint32_t)(r * ROWB + c * 16), Ak + (size_t)r * lda + c * 8);
    }
    #pragma unroll
    for (int t = 0; t < 4; t++) {
        int idx = tid + t * 128;
        int r = idx >> 2, c = idx & 3;
        cp16(b_base + (uint32_t)(r * ROWB + c * 16), Bk + (size_t)r * ldb + c * 8);
    }
}

// Fragments via ldmatrix.x4; A: 4 m16k16 tiles, B: 4 n16k16 tiles (64x64 warp).
__device__ __forceinline__ void compute_stage(
    uint32_t smu, int st, int wm, int wn, int lane, float acc[4][8][4])
{
    const uint32_t As = smu + (uint32_t)(st * STAGE_BYTES);
    const uint32_t Bs = smu + (uint32_t)((NSTAGE + st) * STAGE_BYTES);
    const uint32_t aoff = As + (uint32_t)((wm * 64 + (lane & 15)) * ROWB + (lane >> 4) * 16);
    const int s = lane >> 3;
    const uint32_t boff = Bs + (uint32_t)((wn * 64 + (s >> 1) * 8 + (lane & 7)) * ROWB + (s & 1) * 16);
    #pragma unroll
    for (int ks = 0; ks < 2; ks++) {       // K=32 = 2 x k16
        uint32_t a[4][4], b[4][4];
        #pragma unroll
        for (int mt = 0; mt < 4; mt++)
            ldsm_x4(a[mt], aoff + (uint32_t)(mt * 16 * ROWB + ks * 32));
        #pragma unroll
        for (int np = 0; np < 4; np++)
            ldsm_x4(b[np], boff + (uint32_t)(np * 16 * ROWB + ks * 32));
        #pragma unroll
        for (int mt = 0; mt < 4; mt++) {
            #pragma unroll
            for (int np = 0; np < 4; np++) {
                mma_bf16(acc[mt][np * 2],     a[mt], &b[np][0]);
                mma_bf16(acc[mt][np * 2 + 1], a[mt], &b[np][2]);
            }
        }
    }
}

// 4-stage mainloop (prefetch 3)
__device__ __forceinline__ void run_gemm(
    const __nv_bfloat16* __restrict__ A, int lda,
    const __nv_bfloat16* __restrict__ B, int ldb, int nk,
    uint32_t smu, int wm, int wn, int lane, float acc[4][8][4])
{
    const int pf = (nk < 3) ? nk : 3;
    for (int st = 0; st < pf; st++) {
        load_stage(smu, st, A, lda, B, ldb, st);
        CP_COMMIT();
    }
    for (int kc = 0; kc < nk; kc++) {
        const int rem = nk - 1 - kc;
        if (rem >= 2) CP_WAIT2();
        else if (rem == 1) CP_WAIT1();
        else CP_WAIT0();
        __syncthreads();
        compute_stage(smu, kc & 3, wm, wn, lane, acc);
        const int nxt = kc + 3;
        if (nxt < nk) {
            load_stage(smu, nxt & 3, A, lda, B, ldb, nxt);
            CP_COMMIT();
        }
    }
}

#define GEMM_PREAMBLE() \
    extern __shared__ __align__(16) float sm[]; \
    const uint32_t smu = smem_u32(sm); \
    const int tid = threadIdx.x; \
    const int wid = tid >> 5, lane = tid & 31; \
    const int wm = wid & 1, wn = wid >> 1; \
    const int g = lane >> 2, q4 = lane & 3; \
    float acc[4][8][4]; \
    _Pragma("unroll") for (int i = 0; i < 4; i++) \
    _Pragma("unroll") for (int j = 0; j < 8; j++) \
    _Pragma("unroll") for (int l = 0; l < 4; l++) acc[i][j][l] = 0.f;

// column of acc[mt][nt]: wn*64 + (nt>>1)*16 + (nt&1)*8 + q4*2
#define NT_COL(nt) (wn * 64 + ((nt) >> 1) * 16 + ((nt) & 1) * 8 + q4 * 2)

// ============================================================================
// Kernel 0a: zero g_rowsum
// ============================================================================
__global__ void zero_rowsum_kernel() {
    g_rowsum[blockIdx.x * 1024 + threadIdx.x] = 0.f;
}

// ============================================================================
// Kernel 0b: convert weights fp32 -> bf16 ([Wq;Wk] stacked, Wv)
// ============================================================================
__global__ void convert_w_kernel(const float* __restrict__ Wq,
                                 const float* __restrict__ Wk,
                                 const float* __restrict__ Wv) {
    const int t = blockIdx.x * 256 + threadIdx.x;   // 81920 float4 items
    const float* src;
    __nv_bfloat16* dst;
    int off;
    if (t < 8192)       { src = Wq; dst = g_Wqk;            off = t; }
    else if (t < 16384) { src = Wk; dst = g_Wqk + 64 * C_;  off = t - 8192; }
    else                { src = Wv; dst = g_Wv;             off = t - 16384; }
    float4 v = ((const float4*)src)[off];
    uint32_t* d = (uint32_t*)dst + off * 2;
    d[0] = packbf(v.x, v.y);
    d[1] = packbf(v.z, v.w);
}

// ============================================================================
// Kernel 1: x transpose  x[b][c][n] fp32 -> xT[b][n][c] bf16
// ============================================================================
__global__ void transpose_kernel(const float* __restrict__ x) {
    __shared__ float t[32][33];
    const int b = blockIdx.z;
    const int n0 = blockIdx.x * 32, c0 = blockIdx.y * 32;
    const float* xb = x + (size_t)b * C_ * N_;
    __nv_bfloat16* xtb = g_xT + (size_t)b * N_ * C_;
    const int tx = threadIdx.x, ty = threadIdx.y;   // 32 x 8
    #pragma unroll
    for (int i = 0; i < 32; i += 8)
        t[ty + i][tx] = xb[(size_t)(c0 + ty + i) * N_ + n0 + tx];
    __syncthreads();
    #pragma unroll
    for (int i = 0; i < 32; i += 8)
        xtb[(size_t)(n0 + ty + i) * C_ + c0 + tx] = __float2bfloat16(t[tx][ty + i]);
}

// ============================================================================
// Kernel 2: fused q+k projection.  M=n(128), N=128([Wq;Wk]), K=512.
// ============================================================================
__global__ void __launch_bounds__(128, 2)
qk_proj_kernel(const float* __restrict__ bq, const float* __restrict__ bk) {
    GEMM_PREAMBLE();
    const int b = blockIdx.z;
    const int n0 = blockIdx.x * 128;

    const __nv_bfloat16* A = g_xT + ((size_t)b * N_ + n0) * C_;
    run_gemm(A, C_, g_Wqk, C_, C_ / 32, smu, wm, wn, lane, acc);

    const size_t qkbase = (size_t)b * N_ + n0;
    #pragma unroll
    for (int mt = 0; mt < 4; mt++) {
        const int r0 = wm * 64 + mt * 16 + g;
        #pragma unroll
        for (int nt = 0; nt < 8; nt++) {
            const int col = NT_COL(nt);
            const bool isq = (col < 64);
            const int d = isq ? col : col - 64;
            const float bv0 = isq ? __ldg(bq + d)     : __ldg(bk + d);
            const float bv1 = isq ? __ldg(bq + d + 1) : __ldg(bk + d + 1);
            __nv_bfloat16* dst = isq ? g_q : g_k;
            *(uint32_t*)&dst[(qkbase + r0) * D_ + d] =
                packbf(acc[mt][nt][0] + bv0, acc[mt][nt][1] + bv1);
            *(uint32_t*)&dst[(qkbase + r0 + 8) * D_ + d] =
                packbf(acc[mt][nt][2] + bv0, acc[mt][nt][3] + bv1);
        }
    }
}

// ============================================================================
// Kernel 3: v projection.  M=c(128), N=n(128), K=512.
// ============================================================================
__global__ void __launch_bounds__(128, 2)
v_proj_kernel(const float* __restrict__ bv) {
    GEMM_PREAMBLE();
    const int b = blockIdx.z;
    const int n0 = blockIdx.x * 128;
    const int c0 = blockIdx.y * 128;

    const __nv_bfloat16* A = g_Wv + (size_t)c0 * C_;
    const __nv_bfloat16* Bm = g_xT + ((size_t)b * N_ + n0) * C_;
    run_gemm(A, C_, Bm, C_, C_ / 32, smu, wm, wn, lane, acc);

    #pragma unroll
    for (int mt = 0; mt < 4; mt++) {
        const int r0 = wm * 64 + mt * 16 + g;
        const float bia0 = __ldg(bv + c0 + r0);
        const float bia8 = __ldg(bv + c0 + r0 + 8);
        __nv_bfloat16* row0 = g_v + ((size_t)b * C_ + c0 + r0) * N_ + n0;
        __nv_bfloat16* row8 = row0 + (size_t)8 * N_;
        #pragma unroll
        for (int nt = 0; nt < 8; nt++) {
            const int col = NT_COL(nt);
            *(uint32_t*)&row0[col] = packbf(acc[mt][nt][0] + bia0, acc[mt][nt][1] + bia0);
            *(uint32_t*)&row8[col] = packbf(acc[mt][nt][2] + bia8, acc[mt][nt][3] + bia8);
        }
    }
}

// ============================================================================
// Kernel 4: energy + exp + row-sum.  attn[i][j] = exp(q_i . k_j)  (bf16),
// rowsum[i] += sum_j exp.  exp w/o max-sub is safe (|energy| <~ 12).
// ============================================================================
__global__ void __launch_bounds__(128, 2)
energy_kernel() {
    GEMM_PREAMBLE();
    const int b = blockIdx.z;
    const int j0 = blockIdx.x * 128;
    const int i0 = blockIdx.y * 128;

    float* sums = (float*)((char*)sm + SUMS_BYTE_OFF);
    if (tid < 128) sums[tid] = 0.f;

    const __nv_bfloat16* A = g_q + ((size_t)b * N_ + i0) * D_;
    const __nv_bfloat16* Bm = g_k + ((size_t)b * N_ + j0) * D_;
    run_gemm(A, D_, Bm, D_, D_ / 32, smu, wm, wn, lane, acc);
    __syncthreads();

    #pragma unroll
    for (int mt = 0; mt < 4; mt++) {
        const int r0 = wm * 64 + mt * 16 + g;
        __nv_bfloat16* row0 = g_attn + ((size_t)b * N_ + i0 + r0) * N_ + j0;
        __nv_bfloat16* row8 = row0 + (size_t)8 * N_;
        float p0 = 0.f, p1 = 0.f;
        #pragma unroll
        for (int nt = 0; nt < 8; nt++) {
            const int col = NT_COL(nt);
            float e0 = __expf(acc[mt][nt][0]);
            float e1 = __expf(acc[mt][nt][1]);
            float e2 = __expf(acc[mt][nt][2]);
            float e3 = __expf(acc[mt][nt][3]);
            *(uint32_t*)&row0[col] = packbf(e0, e1);
            *(uint32_t*)&row8[col] = packbf(e2, e3);
            p0 += e0 + e1;
            p1 += e2 + e3;
        }
        p0 += __shfl_xor_sync(0xffffffffu, p0, 1);
        p0 += __shfl_xor_sync(0xffffffffu, p0, 2);
        p1 += __shfl_xor_sync(0xffffffffu, p1, 1);
        p1 += __shfl_xor_sync(0xffffffffu, p1, 2);
        if (q4 == 0) {
            atomicAdd(&sums[r0], p0);
            atomicAdd(&sums[r0 + 8], p1);
        }
    }
    __syncthreads();
    if (tid < 128)
        atomicAdd(&g_rowsum[(size_t)b * N_ + i0 + tid], sums[tid]);
}

// ============================================================================
// Kernel 5: out GEMM.  out[c][i] = gamma/rowsum[i] * sum_j v[c][j] attn[i][j] + x[c][i]
// M=c(128), N=i(128), K=2048.
// ============================================================================
__global__ void __launch_bounds__(128, 2)
out_kernel(const float* __restrict__ x, const float* __restrict__ gamma,
           float* __restrict__ out) {
    GEMM_PREAMBLE();
    const int b = blockIdx.z;
    const int i0 = blockIdx.x * 128;
    const int c0 = blockIdx.y * 128;

    const __nv_bfloat16* A = g_v + ((size_t)b * C_ + c0) * N_;
    const __nv_bfloat16* Bm = g_attn + ((size_t)b * N_ + i0) * N_;
    run_gemm(A, N_, Bm, N_, N_ / 32, smu, wm, wn, lane, acc);

    const float gm = __ldg(gamma);
    float sc[8][2];
    #pragma unroll
    for (int nt = 0; nt < 8; nt++) {
        const int col = i0 + NT_COL(nt);
        sc[nt][0] = gm / __ldg(&g_rowsum[(size_t)b * N_ + col]);
        sc[nt][1] = gm / __ldg(&g_rowsum[(size_t)b * N_ + col + 1]);
    }

    #pragma unroll
    for (int mt = 0; mt < 4; mt++) {
        const int r0 = wm * 64 + mt * 16 + g;
        const size_t base0 = ((size_t)b * C_ + c0 + r0) * N_ + i0;
        const size_t base8 = base0 + (size_t)8 * N_;
        #pragma unroll
        for (int nt = 0; nt < 8; nt++) {
            const int col = NT_COL(nt);
            float2 x0 = *(const float2*)&x[base0 + col];
            float2 x8 = *(const float2*)&x[base8 + col];
            *(float2*)&out[base0 + col] =
                make_float2(sc[nt][0] * acc[mt][nt][0] + x0.x,
                            sc[nt][1] * acc[mt][nt][1] + x0.y);
            *(float2*)&out[base8 + col] =
                make_float2(sc[nt][0] * acc[mt][nt][2] + x8.x,
                            sc[nt][1] * acc[mt][nt][3] + x8.y);
        }
    }
}

// ============================================================================
// Launch — R12 topology (serial prologue; v_proj overlaps qk_proj -> energy).
// ============================================================================
extern "C" void kernel_launch(void* const* d_in, const int* in_sizes, int n_in,
                              void* d_out, int out_size) {
    (void)in_sizes; (void)n_in; (void)out_size;
    const float* x     = (const float*)d_in[0];
    const float* Wq    = (const float*)d_in[1];
    const float* bq    = (const float*)d_in[2];
    const float* Wk    = (const float*)d_in[3];
    const float* bk    = (const float*)d_in[4];
    const float* Wv    = (const float*)d_in[5];
    const float* bv    = (const float*)d_in[6];
    const float* gamma = (const float*)d_in[7];
    float* out = (float*)d_out;

    static cudaStream_t s1 = nullptr;
    static cudaEvent_t ev_fork = nullptr, ev_join = nullptr;
    static bool init_done = false;
    if (!init_done) {
        cudaFuncSetAttribute(qk_proj_kernel, cudaFuncAttributeMaxDynamicSharedMemorySize, SMEM_BYTES);
        cudaFuncSetAttribute(v_proj_kernel,  cudaFuncAttributeMaxDynamicSharedMemorySize, SMEM_BYTES);
        cudaFuncSetAttribute(energy_kernel,  cudaFuncAttributeMaxDynamicSharedMemorySize, SMEM_BYTES);
        cudaFuncSetAttribute(out_kernel,     cudaFuncAttributeMaxDynamicSharedMemorySize, SMEM_BYTES);
        cudaStreamCreateWithFlags(&s1, cudaStreamNonBlocking);
        cudaEventCreateWithFlags(&ev_fork, cudaEventDisableTiming);
        cudaEventCreateWithFlags(&ev_join, cudaEventDisableTiming);
        init_done = true;
    }

    // prologue (stream 0)
    zero_rowsum_kernel<<<B_ * N_ / 1024, 1024>>>();
    convert_w_kernel<<<320, 256>>>(Wq, Wk, Wv);
    transpose_kernel<<<dim3(N_ / 32, C_ / 32, B_), dim3(32, 8)>>>(x);

    // fork: qk_proj -> energy on s1, v_proj on stream 0
    cudaEventRecord(ev_fork, 0);
    cudaStreamWaitEvent(s1, ev_fork, 0);
    qk_proj_kernel<<<dim3(N_ / 128, 1, B_), 128, SMEM_BYTES, s1>>>(bq, bk);
    energy_kernel<<<dim3(N_ / 128, N_ / 128, B_), 128, SMEM_BYTES, s1>>>();
    v_proj_kernel<<<dim3(N_ / 128, C_ / 128, B_), 128, SMEM_BYTES>>>(bv);

    // join: out waits on both branches
    cudaEventRecord(ev_join, s1);
    cudaStreamWaitEvent(0, ev_join, 0);
    out_kernel<<<dim3(N_ / 128, C_ / 128, B_), 128, SMEM_BYTES>>>(x, gamma, out);
}